// round 2
// baseline (speedup 1.0000x reference)
#include <cuda_runtime.h>

#define NB 2
#define NH 16
#define NM 2048
#define ND 1024
#define NDH 64
#define NS 2048
#define NK 256

// Scratch (device globals; no allocations allowed)
__device__ float g_q[NB * NM * ND];
__device__ float g_k[NB * NM * ND];
__device__ float g_v[NB * NM * ND];
__device__ float g_o[NB * NM * ND];
__device__ float g_kp[NB * NK * ND];
__device__ float g_vp[NB * NK * ND];

static __device__ __forceinline__ unsigned long long splat2(float x) {
    unsigned long long r;
    asm("mov.b64 %0, {%1, %1};" : "=l"(r) : "f"(x));
    return r;
}
static __device__ __forceinline__ void fma2(unsigned long long &c,
                                            unsigned long long a,
                                            unsigned long long b) {
    asm("fma.rn.f32x2 %0, %1, %2, %0;" : "+l"(c) : "l"(a), "l"(b));
}
static __device__ __forceinline__ float2 unpk(unsigned long long v) {
    float2 f;
    asm("mov.b64 {%0, %1}, %2;" : "=f"(f.x), "=f"(f.y) : "l"(v));
    return f;
}

// ---------------------------------------------------------------------------
// C[M,N] = A[M,Kd] * B[N,Kd]^T + bias[N]   (both operands row-major, NT GEMM)
// 128x128 tile, BK=8, 256 threads, 8x8 per thread via packed f32x2 FMA.
// ---------------------------------------------------------------------------
__global__ __launch_bounds__(256) void sgemm_nt(
    const float* __restrict__ A, const float* __restrict__ Bm,
    const float* __restrict__ bias, float* __restrict__ C, int Nd, int Kd)
{
    __shared__ float As[8][132];
    __shared__ float Bs[8][132];
    const int tid = threadIdx.x;
    const int bm = blockIdx.x * 128, bn = blockIdx.y * 128;
    const int tr = tid >> 4, tc = tid & 15;
    const int lr = tid >> 1, lk = (tid & 1) << 2;

    unsigned long long acc[2][2][8];
#pragma unroll
    for (int a = 0; a < 2; a++)
#pragma unroll
        for (int p = 0; p < 2; p++)
#pragma unroll
            for (int j = 0; j < 8; j++) acc[a][p][j] = 0ull;

    const float* Ap = A + (size_t)(bm + lr) * Kd + lk;
    const float* Bp = Bm + (size_t)(bn + lr) * Kd + lk;

    for (int kt = 0; kt < Kd; kt += 8) {
        float4 av = *(const float4*)(Ap + kt);
        float4 bv = *(const float4*)(Bp + kt);
        As[lk + 0][lr] = av.x; As[lk + 1][lr] = av.y;
        As[lk + 2][lr] = av.z; As[lk + 3][lr] = av.w;
        Bs[lk + 0][lr] = bv.x; Bs[lk + 1][lr] = bv.y;
        Bs[lk + 2][lr] = bv.z; Bs[lk + 3][lr] = bv.w;
        __syncthreads();
#pragma unroll
        for (int k = 0; k < 8; k++) {
            ulonglong2 a0 = *(const ulonglong2*)&As[k][tr * 4];
            ulonglong2 a1 = *(const ulonglong2*)&As[k][64 + tr * 4];
            float4 b0 = *(const float4*)&Bs[k][tc * 4];
            float4 b1 = *(const float4*)&Bs[k][64 + tc * 4];
            unsigned long long bs[8] = {splat2(b0.x), splat2(b0.y), splat2(b0.z), splat2(b0.w),
                                        splat2(b1.x), splat2(b1.y), splat2(b1.z), splat2(b1.w)};
#pragma unroll
            for (int j = 0; j < 8; j++) {
                fma2(acc[0][0][j], a0.x, bs[j]);
                fma2(acc[0][1][j], a0.y, bs[j]);
                fma2(acc[1][0][j], a1.x, bs[j]);
                fma2(acc[1][1][j], a1.y, bs[j]);
            }
        }
        __syncthreads();
    }

    float accf[2][4][8];
#pragma unroll
    for (int a = 0; a < 2; a++)
#pragma unroll
        for (int p = 0; p < 2; p++)
#pragma unroll
            for (int j = 0; j < 8; j++) {
                float2 u = unpk(acc[a][p][j]);
                accf[a][p * 2 + 0][j] = u.x;
                accf[a][p * 2 + 1][j] = u.y;
            }
#pragma unroll
    for (int a = 0; a < 2; a++)
#pragma unroll
        for (int rr = 0; rr < 4; rr++) {
            int row = bm + a * 64 + tr * 4 + rr;
            float* cp = C + (size_t)row * Nd + bn;
#pragma unroll
            for (int ch = 0; ch < 2; ch++) {
                int cb = ch * 64 + tc * 4;
                float4 o;
                o.x = accf[a][rr][ch * 4 + 0] + bias[bn + cb + 0];
                o.y = accf[a][rr][ch * 4 + 1] + bias[bn + cb + 1];
                o.z = accf[a][rr][ch * 4 + 2] + bias[bn + cb + 2];
                o.w = accf[a][rr][ch * 4 + 3] + bias[bn + cb + 3];
                *(float4*)(cp + cb) = o;
            }
        }
}

// ---------------------------------------------------------------------------
// Linformer projections: for z in {Ek@k[0], Ek@k[1], Ev@v[0], Ev@v[1]}:
//   C[256,1024] = A[256,2048] * B[2048,1024]   (NN GEMM, no bias)
// ---------------------------------------------------------------------------
__global__ __launch_bounds__(256) void proj_nn(const float* __restrict__ Ekm,
                                               const float* __restrict__ Evm)
{
    __shared__ float As[8][132];
    __shared__ float Bs[8][132];
    const int tid = threadIdx.x;
    const int zz = blockIdx.z;
    const float* A = (zz < 2) ? Ekm : Evm;
    const float* Bm = ((zz < 2) ? g_k : g_v) + (size_t)(zz & 1) * NM * ND;
    float* C = ((zz < 2) ? g_kp : g_vp) + (size_t)(zz & 1) * NK * ND;
    const int Kd = NM, Nd = ND;
    const int bm = blockIdx.x * 128, bn = blockIdx.y * 128;
    const int tr = tid >> 4, tc = tid & 15;
    const int lr = tid >> 1, lk = (tid & 1) << 2;
    const int br = tid >> 5, bc = (tid & 31) << 2;

    unsigned long long acc[2][2][8];
#pragma unroll
    for (int a = 0; a < 2; a++)
#pragma unroll
        for (int p = 0; p < 2; p++)
#pragma unroll
            for (int j = 0; j < 8; j++) acc[a][p][j] = 0ull;

    const float* Ap = A + (size_t)(bm + lr) * Kd + lk;

    for (int kt = 0; kt < Kd; kt += 8) {
        float4 av = *(const float4*)(Ap + kt);
        As[lk + 0][lr] = av.x; As[lk + 1][lr] = av.y;
        As[lk + 2][lr] = av.z; As[lk + 3][lr] = av.w;
        float4 bv = *(const float4*)(Bm + (size_t)(kt + br) * Nd + bn + bc);
        *(float4*)&Bs[br][bc] = bv;
        __syncthreads();
#pragma unroll
        for (int k = 0; k < 8; k++) {
            ulonglong2 a0 = *(const ulonglong2*)&As[k][tr * 4];
            ulonglong2 a1 = *(const ulonglong2*)&As[k][64 + tr * 4];
            float4 b0 = *(const float4*)&Bs[k][tc * 4];
            float4 b1 = *(const float4*)&Bs[k][64 + tc * 4];
            unsigned long long bs[8] = {splat2(b0.x), splat2(b0.y), splat2(b0.z), splat2(b0.w),
                                        splat2(b1.x), splat2(b1.y), splat2(b1.z), splat2(b1.w)};
#pragma unroll
            for (int j = 0; j < 8; j++) {
                fma2(acc[0][0][j], a0.x, bs[j]);
                fma2(acc[0][1][j], a0.y, bs[j]);
                fma2(acc[1][0][j], a1.x, bs[j]);
                fma2(acc[1][1][j], a1.y, bs[j]);
            }
        }
        __syncthreads();
    }

    float accf[2][4][8];
#pragma unroll
    for (int a = 0; a < 2; a++)
#pragma unroll
        for (int p = 0; p < 2; p++)
#pragma unroll
            for (int j = 0; j < 8; j++) {
                float2 u = unpk(acc[a][p][j]);
                accf[a][p * 2 + 0][j] = u.x;
                accf[a][p * 2 + 1][j] = u.y;
            }
#pragma unroll
    for (int a = 0; a < 2; a++)
#pragma unroll
        for (int rr = 0; rr < 4; rr++) {
            int row = bm + a * 64 + tr * 4 + rr;
            float* cp = C + (size_t)row * Nd + bn;
#pragma unroll
            for (int ch = 0; ch < 2; ch++) {
                int cb = ch * 64 + tc * 4;
                float4 o;
                o.x = accf[a][rr][ch * 4 + 0];
                o.y = accf[a][rr][ch * 4 + 1];
                o.z = accf[a][rr][ch * 4 + 2];
                o.w = accf[a][rr][ch * 4 + 3];
                *(float4*)(cp + cb) = o;
            }
        }
}

// ---------------------------------------------------------------------------
// Fused attention per (b, h, 64-row m tile):
//   scores[64,256] = (geom+content)[64,2048] @ Ek^T + (q/8)[64,64] @ kproj^T
//   softmax over 256, out[64,64] = attn @ vproj  -> g_o (B,M,H,dh layout)
// 256 threads; scores acc held in registers as packed f32x2 row-pairs.
// ---------------------------------------------------------------------------
#define AST 72
#define BST 264
#define ATST 264
#define SMF_FLOATS (64 * ATST + 16 * AST)   // 18048 floats = 72192 B

__global__ __launch_bounds__(256) void attn_fused(
    const float* __restrict__ geom, const float* __restrict__ cont,
    const float* __restrict__ Ekm)
{
    extern __shared__ float sm[];
    float* As = sm;                 // [16][AST]
    float* Bs = sm + 16 * AST;      // [16][BST]
    const int m0 = blockIdx.x * 64;
    const int h = blockIdx.y, b = blockIdx.z;
    const int tid = threadIdx.x;
    const int tr = tid >> 5, tc = tid & 31;      // warp / lane
    const int lrow = tid >> 2, lcg = (tid & 3) << 2;

    unsigned long long acc[4][8];
#pragma unroll
    for (int p = 0; p < 4; p++)
#pragma unroll
        for (int j = 0; j < 8; j++) acc[p][j] = 0ull;

    const float* gp = geom + ((size_t)(b * NH + h) * NM + m0) * NS;
    const float* cp = cont + ((size_t)(b * NH + h) * NM + m0) * NS;

    // ---- bias-sum @ Ek^T over S=2048 ----
    for (int s = 0; s < NS; s += 16) {
        const float* ep = Ekm + (size_t)tid * NS + s;
        float4 e0 = *(const float4*)(ep + 0);
        float4 e1 = *(const float4*)(ep + 4);
        float4 e2 = *(const float4*)(ep + 8);
        float4 e3 = *(const float4*)(ep + 12);
        Bs[0 * BST + tid] = e0.x; Bs[1 * BST + tid] = e0.y;
        Bs[2 * BST + tid] = e0.z; Bs[3 * BST + tid] = e0.w;
        Bs[4 * BST + tid] = e1.x; Bs[5 * BST + tid] = e1.y;
        Bs[6 * BST + tid] = e1.z; Bs[7 * BST + tid] = e1.w;
        Bs[8 * BST + tid] = e2.x; Bs[9 * BST + tid] = e2.y;
        Bs[10 * BST + tid] = e2.z; Bs[11 * BST + tid] = e2.w;
        Bs[12 * BST + tid] = e3.x; Bs[13 * BST + tid] = e3.y;
        Bs[14 * BST + tid] = e3.z; Bs[15 * BST + tid] = e3.w;

        float4 g = *(const float4*)(gp + (size_t)lrow * NS + s + lcg);
        float4 c = *(const float4*)(cp + (size_t)lrow * NS + s + lcg);
        As[(lcg + 0) * AST + lrow] = g.x + c.x;
        As[(lcg + 1) * AST + lrow] = g.y + c.y;
        As[(lcg + 2) * AST + lrow] = g.z + c.z;
        As[(lcg + 3) * AST + lrow] = g.w + c.w;
        __syncthreads();
#pragma unroll
        for (int ss = 0; ss < 16; ss++) {
            ulonglong2 a0 = *(const ulonglong2*)&As[ss * AST + tr * 8];
            ulonglong2 a1 = *(const ulonglong2*)&As[ss * AST + tr * 8 + 4];
            float4 b0 = *(const float4*)&Bs[ss * BST + tc * 4];
            float4 b1 = *(const float4*)&Bs[ss * BST + 128 + tc * 4];
            unsigned long long bs[8] = {splat2(b0.x), splat2(b0.y), splat2(b0.z), splat2(b0.w),
                                        splat2(b1.x), splat2(b1.y), splat2(b1.z), splat2(b1.w)};
#pragma unroll
            for (int j = 0; j < 8; j++) {
                fma2(acc[0][j], a0.x, bs[j]);
                fma2(acc[1][j], a0.y, bs[j]);
                fma2(acc[2][j], a1.x, bs[j]);
                fma2(acc[3][j], a1.y, bs[j]);
            }
        }
        __syncthreads();
    }

    // ---- + (q * 1/sqrt(dh)) @ kproj^T over dh=64 ----
    const float* qp = g_q + ((size_t)b * NM + m0) * ND + h * NDH;
    const float* kp = g_kp + ((size_t)b * NK + tid) * ND + h * NDH;
    for (int d0 = 0; d0 < NDH; d0 += 16) {
        const float* ep = kp + d0;
        float4 e0 = *(const float4*)(ep + 0);
        float4 e1 = *(const float4*)(ep + 4);
        float4 e2 = *(const float4*)(ep + 8);
        float4 e3 = *(const float4*)(ep + 12);
        Bs[0 * BST + tid] = e0.x; Bs[1 * BST + tid] = e0.y;
        Bs[2 * BST + tid] = e0.z; Bs[3 * BST + tid] = e0.w;
        Bs[4 * BST + tid] = e1.x; Bs[5 * BST + tid] = e1.y;
        Bs[6 * BST + tid] = e1.z; Bs[7 * BST + tid] = e1.w;
        Bs[8 * BST + tid] = e2.x; Bs[9 * BST + tid] = e2.y;
        Bs[10 * BST + tid] = e2.z; Bs[11 * BST + tid] = e2.w;
        Bs[12 * BST + tid] = e3.x; Bs[13 * BST + tid] = e3.y;
        Bs[14 * BST + tid] = e3.z; Bs[15 * BST + tid] = e3.w;

        float4 qv = *(const float4*)(qp + (size_t)lrow * ND + d0 + lcg);
        As[(lcg + 0) * AST + lrow] = qv.x * 0.125f;
        As[(lcg + 1) * AST + lrow] = qv.y * 0.125f;
        As[(lcg + 2) * AST + lrow] = qv.z * 0.125f;
        As[(lcg + 3) * AST + lrow] = qv.w * 0.125f;
        __syncthreads();
#pragma unroll
        for (int ss = 0; ss < 16; ss++) {
            ulonglong2 a0 = *(const ulonglong2*)&As[ss * AST + tr * 8];
            ulonglong2 a1 = *(const ulonglong2*)&As[ss * AST + tr * 8 + 4];
            float4 b0 = *(const float4*)&Bs[ss * BST + tc * 4];
            float4 b1 = *(const float4*)&Bs[ss * BST + 128 + tc * 4];
            unsigned long long bs[8] = {splat2(b0.x), splat2(b0.y), splat2(b0.z), splat2(b0.w),
                                        splat2(b1.x), splat2(b1.y), splat2(b1.z), splat2(b1.w)};
#pragma unroll
            for (int j = 0; j < 8; j++) {
                fma2(acc[0][j], a0.x, bs[j]);
                fma2(acc[1][j], a0.y, bs[j]);
                fma2(acc[2][j], a1.x, bs[j]);
                fma2(acc[3][j], a1.y, bs[j]);
            }
        }
        __syncthreads();
    }

    // ---- softmax (each warp owns 8 full rows; lane tc holds 8 cols) ----
    float sc[8][8];
#pragma unroll
    for (int p = 0; p < 4; p++)
#pragma unroll
        for (int j = 0; j < 8; j++) {
            float2 u = unpk(acc[p][j]);
            sc[2 * p + 0][j] = u.x;
            sc[2 * p + 1][j] = u.y;
        }
#pragma unroll
    for (int r = 0; r < 8; r++) {
        float mx = sc[r][0];
#pragma unroll
        for (int j = 1; j < 8; j++) mx = fmaxf(mx, sc[r][j]);
#pragma unroll
        for (int off = 16; off > 0; off >>= 1)
            mx = fmaxf(mx, __shfl_xor_sync(0xffffffffu, mx, off));
        float sum = 0.f;
#pragma unroll
        for (int j = 0; j < 8; j++) { sc[r][j] = __expf(sc[r][j] - mx); sum += sc[r][j]; }
#pragma unroll
        for (int off = 16; off > 0; off >>= 1)
            sum += __shfl_xor_sync(0xffffffffu, sum, off);
        float inv = 1.f / sum;
#pragma unroll
        for (int j = 0; j < 8; j++) sc[r][j] *= inv;
    }

    // ---- attn to smem, then out = attn @ vproj ----
    float* attn = sm;               // [64][ATST], overlays As/Bs (all reads done)
    float* Vs = sm + 64 * ATST;     // [16][72]
#pragma unroll
    for (int r = 0; r < 8; r++) {
#pragma unroll
        for (int j = 0; j < 8; j++) {
            int col = (j < 4) ? (tc * 4 + j) : (128 + tc * 4 + (j - 4));
            attn[(tr * 8 + r) * ATST + col] = sc[r][j];
        }
    }

    const int r2 = tid >> 4, c2 = tid & 15;
    const float* vp = g_vp + (size_t)b * NK * ND + h * NDH;
    float o[4][4];
#pragma unroll
    for (int i = 0; i < 4; i++)
#pragma unroll
        for (int j = 0; j < 4; j++) o[i][j] = 0.f;

    for (int k0 = 0; k0 < NK; k0 += 16) {
        __syncthreads();   // iter0: attn visible; later: prior Vs reads done
        *(float4*)&Vs[(tid >> 4) * AST + ((tid & 15) << 2)] =
            *(const float4*)(vp + (size_t)(k0 + (tid >> 4)) * ND + ((tid & 15) << 2));
        __syncthreads();
#pragma unroll
        for (int j = 0; j < 16; j++) {
            float4 bb = *(const float4*)&Vs[j * AST + c2 * 4];
            float a0 = attn[(r2 * 4 + 0) * ATST + k0 + j];
            float a1 = attn[(r2 * 4 + 1) * ATST + k0 + j];
            float a2 = attn[(r2 * 4 + 2) * ATST + k0 + j];
            float a3 = attn[(r2 * 4 + 3) * ATST + k0 + j];
            o[0][0] += a0 * bb.x; o[0][1] += a0 * bb.y; o[0][2] += a0 * bb.z; o[0][3] += a0 * bb.w;
            o[1][0] += a1 * bb.x; o[1][1] += a1 * bb.y; o[1][2] += a1 * bb.z; o[1][3] += a1 * bb.w;
            o[2][0] += a2 * bb.x; o[2][1] += a2 * bb.y; o[2][2] += a2 * bb.z; o[2][3] += a2 * bb.w;
            o[3][0] += a3 * bb.x; o[3][1] += a3 * bb.y; o[3][2] += a3 * bb.z; o[3][3] += a3 * bb.w;
        }
    }

    float* op = g_o + ((size_t)b * NM + m0) * ND + h * NDH;
#pragma unroll
    for (int i = 0; i < 4; i++) {
        float4 st = make_float4(o[i][0], o[i][1], o[i][2], o[i][3]);
        *(float4*)(op + (size_t)(r2 * 4 + i) * ND + c2 * 4) = st;
    }
}

// ---------------------------------------------------------------------------
extern "C" void kernel_launch(void* const* d_in, const int* in_sizes, int n_in,
                              void* d_out, int out_size)
{
    (void)out_size;
    // Robust positional matching by element count (tolerates scalar/bool packing):
    const float* zp = nullptr;
    const float* geom = nullptr;
    const float* cont = nullptr;
    const float* W[4] = {nullptr, nullptr, nullptr, nullptr};   // Wq, Wk, Wv, Wo
    const float* bias[4] = {nullptr, nullptr, nullptr, nullptr}; // bq, bk, bv, bo
    const float* E[2] = {nullptr, nullptr};                      // Ek, Ev
    int wi = 0, bi = 0, ei = 0;
    for (int i = 0; i < n_in; i++) {
        long sz = (long)in_sizes[i];
        if (sz == (long)NB * NM * ND) {
            if (!zp) zp = (const float*)d_in[i];
        } else if (sz == (long)NB * NH * NM * NS) {
            if (!geom) geom = (const float*)d_in[i];
            else if (!cont) cont = (const float*)d_in[i];
        } else if (sz == (long)ND * ND) {
            if (wi < 4) W[wi++] = (const float*)d_in[i];
        } else if (sz == (long)ND) {
            if (bi < 4) bias[bi++] = (const float*)d_in[i];
        } else if (sz == (long)NK * NS) {
            if (ei < 2) E[ei++] = (const float*)d_in[i];
        }
    }
    float* out = (float*)d_out;

    float *q, *k, *v, *o;
    cudaGetSymbolAddress((void**)&q, g_q);
    cudaGetSymbolAddress((void**)&k, g_k);
    cudaGetSymbolAddress((void**)&v, g_v);
    cudaGetSymbolAddress((void**)&o, g_o);

    dim3 thr(256);
    dim3 gproj(NB * NM / 128, ND / 128);     // (32, 8)
    sgemm_nt<<<gproj, thr>>>(zp, W[0], bias[0], q, ND, ND);
    sgemm_nt<<<gproj, thr>>>(zp, W[1], bias[1], k, ND, ND);
    sgemm_nt<<<gproj, thr>>>(zp, W[2], bias[2], v, ND, ND);
    proj_nn<<<dim3(NK / 128, ND / 128, 4), thr>>>(E[0], E[1]);

    cudaFuncSetAttribute(attn_fused, cudaFuncAttributeMaxDynamicSharedMemorySize,
                         SMF_FLOATS * (int)sizeof(float));
    attn_fused<<<dim3(NM / 64, NH, NB), thr, SMF_FLOATS * sizeof(float)>>>(geom, cont, E[0]);

    sgemm_nt<<<gproj, thr>>>(o, W[3], bias[3], out, ND, ND);
}

// round 4
// speedup vs baseline: 3.7075x; 3.7075x over previous
#include <cuda_runtime.h>

#define NB 2
#define NH 16
#define NM 2048
#define ND 1024
#define NDH 64
#define NS 2048
#define NK 256

// Scratch (device globals; no allocations allowed)
__device__ float g_q[NB * NM * ND];
__device__ float g_k[NB * NM * ND];
__device__ float g_v[NB * NM * ND];
__device__ float g_o[NB * NM * ND];
__device__ float g_kp[NB * NK * ND];
__device__ float g_vp[NB * NK * ND];
__device__ float g_sb[NB * NH * NM * NK];          // bias scores [B,H,M,K] (67MB)
__device__ float g_pp[16 * NK * ND];               // proj split-K partials

// ---------------- packed f32x2 helpers (SIMT kernels) ----------------
static __device__ __forceinline__ unsigned long long splat2(float x) {
    unsigned long long r;
    asm("mov.b64 %0, {%1, %1};" : "=l"(r) : "f"(x));
    return r;
}
static __device__ __forceinline__ void fma2(unsigned long long &c,
                                            unsigned long long a,
                                            unsigned long long b) {
    asm("fma.rn.f32x2 %0, %1, %2, %0;" : "+l"(c) : "l"(a), "l"(b));
}
static __device__ __forceinline__ float2 unpk(unsigned long long v) {
    float2 f;
    asm("mov.b64 {%0, %1}, %2;" : "=f"(f.x), "=f"(f.y) : "l"(v));
    return f;
}

// ---------------- mma.sync tf32 helpers ----------------
static __device__ __forceinline__ unsigned s2u(const void* p) {
    unsigned a;
    asm("{ .reg .u64 t; cvta.to.shared.u64 t, %1; cvt.u32.u64 %0, t; }" : "=r"(a) : "l"(p));
    return a;
}
static __device__ __forceinline__ unsigned f2tf(float f) {
    unsigned u;
    asm("cvt.rna.tf32.f32 %0, %1;" : "=r"(u) : "f"(f));
    return u;
}
static __device__ __forceinline__ void mma8(float* c, const unsigned* a, const unsigned* b) {
    asm volatile(
        "mma.sync.aligned.m16n8k8.row.col.f32.tf32.tf32.f32 "
        "{%0,%1,%2,%3}, {%4,%5,%6,%7}, {%8,%9}, {%0,%1,%2,%3};"
        : "+f"(c[0]), "+f"(c[1]), "+f"(c[2]), "+f"(c[3])
        : "r"(a[0]), "r"(a[1]), "r"(a[2]), "r"(a[3]), "r"(b[0]), "r"(b[1]));
}
static __device__ __forceinline__ void cpasync16(unsigned dst, const void* src) {
    asm volatile("cp.async.cg.shared.global [%0], [%1], 16;" :: "r"(dst), "l"(src) : "memory");
}

#define BM 128
#define BN 128
#define BK 32
#define BKP 36   // padded row stride (floats)
#define TCSM ((2 * BM * BKP + 2 * BN * BKP) * 4)   // 73728 bytes

// ---------------------------------------------------------------------------
// C[m0..+128, n0..+128] = (A (+A2)) @ B^T (+bias)  via tf32 mma.sync.
// A: [M,Kd] row-major fp32; B: [Nrows,Kd] row-major fp32; Kd % 32 == 0.
// 256 threads = 8 warps (2 x 4); warp tile 64x32; cp.async double buffer.
// ---------------------------------------------------------------------------
__global__ __launch_bounds__(256) void tc32_nt(
    const float* __restrict__ A, const float* __restrict__ A2,
    const float* __restrict__ Bm, const float* __restrict__ bias,
    float* __restrict__ C, int Nld, int Kd)
{
    extern __shared__ float smf[];
    float* As = smf;                    // [2][BM][BKP]
    float* Bs = smf + 2 * BM * BKP;     // [2][BN][BKP]
    const int tid = threadIdx.x;
    const int lane = tid & 31, wid = tid >> 5;
    const size_t m0 = (size_t)blockIdx.x * BM;
    const int n0 = blockIdx.y * BN;

    const int lr = tid >> 1;            // 0..127 (row within tile)
    const int lc = (tid & 1) * 16;      // 0 | 16 (k offset)

    const float* Ag = A + (m0 + lr) * (size_t)Kd + lc;
    const float* A2g = A2 ? A2 + (m0 + lr) * (size_t)Kd + lc : (const float*)0;
    const float* Bg = Bm + (size_t)(n0 + lr) * Kd + lc;

    float* asw = As + lr * BKP + lc;
    float* bsw = Bs + lr * BKP + lc;

    auto loadtile = [&](int k0, int buf) {
        float* ad = asw + buf * BM * BKP;
        float* bd = bsw + buf * BN * BKP;
        if (A2g) {
#pragma unroll
            for (int i = 0; i < 4; i++) {
                float4 v = *(const float4*)(Ag + k0 + i * 4);
                float4 w = *(const float4*)(A2g + k0 + i * 4);
                ad[i * 4 + 0] = v.x + w.x; ad[i * 4 + 1] = v.y + w.y;
                ad[i * 4 + 2] = v.z + w.z; ad[i * 4 + 3] = v.w + w.w;
            }
        } else {
#pragma unroll
            for (int i = 0; i < 4; i++)
                cpasync16(s2u(ad + i * 4), Ag + k0 + i * 4);
        }
#pragma unroll
        for (int i = 0; i < 4; i++)
            cpasync16(s2u(bd + i * 4), Bg + k0 + i * 4);
    };

    const int wm = (wid >> 2) * 64, wn = (wid & 3) * 32;
    const int gr = lane >> 2, gc = lane & 3;

    float acc[4][4][4];
#pragma unroll
    for (int mt = 0; mt < 4; mt++)
#pragma unroll
        for (int nt = 0; nt < 4; nt++)
#pragma unroll
            for (int e = 0; e < 4; e++) acc[mt][nt][e] = 0.f;

    loadtile(0, 0);
    asm volatile("cp.async.commit_group;" ::: "memory");

    const int nk = Kd / BK;
    for (int i = 0; i < nk; i++) {
        if (i + 1 < nk) {
            loadtile((i + 1) * BK, (i + 1) & 1);
            asm volatile("cp.async.commit_group;" ::: "memory");
            asm volatile("cp.async.wait_group 1;" ::: "memory");
        } else {
            asm volatile("cp.async.wait_group 0;" ::: "memory");
        }
        __syncthreads();

        const float* ab = As + (i & 1) * BM * BKP + (wm + gr) * BKP;
        const float* bb = Bs + (i & 1) * BN * BKP + (wn + gr) * BKP;
#pragma unroll
        for (int k8 = 0; k8 < 4; k8++) {
            const int k0 = k8 * 8;
            unsigned af[4][4], bf[4][2];
#pragma unroll
            for (int mt = 0; mt < 4; mt++) {
                const float* p = ab + mt * 16 * BKP + k0 + gc;
                af[mt][0] = f2tf(p[0]);
                af[mt][1] = f2tf(p[8 * BKP]);
                af[mt][2] = f2tf(p[4]);
                af[mt][3] = f2tf(p[8 * BKP + 4]);
            }
#pragma unroll
            for (int nt = 0; nt < 4; nt++) {
                const float* p = bb + nt * 8 * BKP + k0 + gc;
                bf[nt][0] = f2tf(p[0]);
                bf[nt][1] = f2tf(p[4]);
            }
#pragma unroll
            for (int mt = 0; mt < 4; mt++)
#pragma unroll
                for (int nt = 0; nt < 4; nt++)
                    mma8(acc[mt][nt], af[mt], bf[nt]);
        }
        __syncthreads();
    }

    // epilogue
#pragma unroll
    for (int mt = 0; mt < 4; mt++) {
        const size_t r = m0 + wm + mt * 16 + gr;
        float* cp0 = C + r * (size_t)Nld;
        float* cp1 = C + (r + 8) * (size_t)Nld;
#pragma unroll
        for (int nt = 0; nt < 4; nt++) {
            const int c = n0 + wn + nt * 8 + 2 * gc;
            float b0 = bias ? bias[c] : 0.f;
            float b1 = bias ? bias[c + 1] : 0.f;
            float2 v0 = make_float2(acc[mt][nt][0] + b0, acc[mt][nt][1] + b1);
            float2 v1 = make_float2(acc[mt][nt][2] + b0, acc[mt][nt][3] + b1);
            *(float2*)(cp0 + c) = v0;
            *(float2*)(cp1 + c) = v1;
        }
    }
}

// ---------------------------------------------------------------------------
// Linformer projections with split-K x4 (deterministic):
// bz = gemm*4 + split; gemm 0,1: Ek@k[b]; 2,3: Ev@v[b]. Partial -> g_pp[bz].
// ---------------------------------------------------------------------------
__global__ __launch_bounds__(256) void proj_nn2(const float* __restrict__ Ekm,
                                                const float* __restrict__ Evm)
{
    __shared__ float As[8][132];
    __shared__ float Bs[8][132];
    const int tid = threadIdx.x;
    const int bz = blockIdx.z;
    const int zz = bz >> 2, sp = bz & 3;
    const int kstart = sp * 512;
    const float* A = (zz < 2) ? Ekm : Evm;
    const float* Bm = ((zz < 2) ? g_k : g_v) + (size_t)(zz & 1) * NM * ND;
    float* C = g_pp + (size_t)bz * (NK * ND);
    const int Kd = NM, Nd = ND;
    const int bm = blockIdx.x * 128, bn = blockIdx.y * 128;
    const int tr = tid >> 4, tc = tid & 15;
    const int lr = tid >> 1, lk = (tid & 1) << 2;
    const int br = tid >> 5, bc = (tid & 31) << 2;

    unsigned long long acc[2][2][8];
#pragma unroll
    for (int a = 0; a < 2; a++)
#pragma unroll
        for (int p = 0; p < 2; p++)
#pragma unroll
            for (int j = 0; j < 8; j++) acc[a][p][j] = 0ull;

    const float* Ap = A + (size_t)(bm + lr) * Kd + kstart + lk;

    for (int kt = 0; kt < 512; kt += 8) {
        float4 av = *(const float4*)(Ap + kt);
        As[lk + 0][lr] = av.x; As[lk + 1][lr] = av.y;
        As[lk + 2][lr] = av.z; As[lk + 3][lr] = av.w;
        float4 bv = *(const float4*)(Bm + (size_t)(kstart + kt + br) * Nd + bn + bc);
        *(float4*)&Bs[br][bc] = bv;
        __syncthreads();
#pragma unroll
        for (int k = 0; k < 8; k++) {
            ulonglong2 a0 = *(const ulonglong2*)&As[k][tr * 4];
            ulonglong2 a1 = *(const ulonglong2*)&As[k][64 + tr * 4];
            float4 b0 = *(const float4*)&Bs[k][tc * 4];
            float4 b1 = *(const float4*)&Bs[k][64 + tc * 4];
            unsigned long long bs[8] = {splat2(b0.x), splat2(b0.y), splat2(b0.z), splat2(b0.w),
                                        splat2(b1.x), splat2(b1.y), splat2(b1.z), splat2(b1.w)};
#pragma unroll
            for (int j = 0; j < 8; j++) {
                fma2(acc[0][0][j], a0.x, bs[j]);
                fma2(acc[0][1][j], a0.y, bs[j]);
                fma2(acc[1][0][j], a1.x, bs[j]);
                fma2(acc[1][1][j], a1.y, bs[j]);
            }
        }
        __syncthreads();
    }

    float accf[2][4][8];
#pragma unroll
    for (int a = 0; a < 2; a++)
#pragma unroll
        for (int p = 0; p < 2; p++)
#pragma unroll
            for (int j = 0; j < 8; j++) {
                float2 u = unpk(acc[a][p][j]);
                accf[a][p * 2 + 0][j] = u.x;
                accf[a][p * 2 + 1][j] = u.y;
            }
#pragma unroll
    for (int a = 0; a < 2; a++)
#pragma unroll
        for (int rr = 0; rr < 4; rr++) {
            int row = bm + a * 64 + tr * 4 + rr;
            float* cp = C + (size_t)row * Nd + bn;
#pragma unroll
            for (int ch = 0; ch < 2; ch++) {
                int cb = ch * 64 + tc * 4;
                float4 o;
                o.x = accf[a][rr][ch * 4 + 0];
                o.y = accf[a][rr][ch * 4 + 1];
                o.z = accf[a][rr][ch * 4 + 2];
                o.w = accf[a][rr][ch * 4 + 3];
                *(float4*)(cp + cb) = o;
            }
        }
}

__global__ __launch_bounds__(256) void proj_reduce()
{
    const size_t i = (size_t)blockIdx.x * 256 + threadIdx.x;   // over 4*NK*ND
    const int zz = (int)(i / (NK * ND));
    const size_t r = i - (size_t)zz * (NK * ND);
    const size_t base = (size_t)(zz * 4) * (NK * ND) + r;
    float s = g_pp[base] + g_pp[base + (size_t)NK * ND] +
              g_pp[base + 2 * (size_t)NK * ND] + g_pp[base + 3 * (size_t)NK * ND];
    float* dst = (zz < 2) ? g_kp : g_vp;
    dst[(size_t)(zz & 1) * NK * ND + r] = s;
}

// ---------------------------------------------------------------------------
// Fused attention per (b, h, 64-row m tile):
//   scores[64,256] = g_sb (precomputed bias scores) + (q/8)[64,64] @ kproj^T
//   softmax over 256, out[64,64] = attn @ vproj  -> g_o (B,M,H,dh layout)
// ---------------------------------------------------------------------------
#define AST 72
#define BST 264
#define ATST 264
#define SMF_FLOATS (64 * ATST + 16 * AST)   // 18048 floats = 72192 B

__global__ __launch_bounds__(256) void attn2()
{
    extern __shared__ float sm[];
    float* As = sm;                 // [16][AST]
    float* Bs = sm + 16 * AST;      // [16][BST]
    const int m0 = blockIdx.x * 64;
    const int h = blockIdx.y, b = blockIdx.z;
    const int tid = threadIdx.x;
    const int tr = tid >> 5, tc = tid & 31;
    const int lrow = tid >> 2, lcg = (tid & 3) << 2;

    unsigned long long acc[4][8];
#pragma unroll
    for (int p = 0; p < 4; p++)
#pragma unroll
        for (int j = 0; j < 8; j++) acc[p][j] = 0ull;

    // ---- (q * 1/sqrt(dh)) @ kproj^T over dh=64 ----
    const float* qp = g_q + ((size_t)b * NM + m0) * ND + h * NDH;
    const float* kp = g_kp + ((size_t)b * NK + tid) * ND + h * NDH;
    for (int d0 = 0; d0 < NDH; d0 += 16) {
        const float* ep = kp + d0;
        float4 e0 = *(const float4*)(ep + 0);
        float4 e1 = *(const float4*)(ep + 4);
        float4 e2 = *(const float4*)(ep + 8);
        float4 e3 = *(const float4*)(ep + 12);
        Bs[0 * BST + tid] = e0.x;  Bs[1 * BST + tid] = e0.y;
        Bs[2 * BST + tid] = e0.z;  Bs[3 * BST + tid] = e0.w;
        Bs[4 * BST + tid] = e1.x;  Bs[5 * BST + tid] = e1.y;
        Bs[6 * BST + tid] = e1.z;  Bs[7 * BST + tid] = e1.w;
        Bs[8 * BST + tid] = e2.x;  Bs[9 * BST + tid] = e2.y;
        Bs[10 * BST + tid] = e2.z; Bs[11 * BST + tid] = e2.w;
        Bs[12 * BST + tid] = e3.x; Bs[13 * BST + tid] = e3.y;
        Bs[14 * BST + tid] = e3.z; Bs[15 * BST + tid] = e3.w;

        float4 qv = *(const float4*)(qp + (size_t)lrow * ND + d0 + lcg);
        As[(lcg + 0) * AST + lrow] = qv.x * 0.125f;
        As[(lcg + 1) * AST + lrow] = qv.y * 0.125f;
        As[(lcg + 2) * AST + lrow] = qv.z * 0.125f;
        As[(lcg + 3) * AST + lrow] = qv.w * 0.125f;
        __syncthreads();
#pragma unroll
        for (int ss = 0; ss < 16; ss++) {
            ulonglong2 a0 = *(const ulonglong2*)&As[ss * AST + tr * 8];
            ulonglong2 a1 = *(const ulonglong2*)&As[ss * AST + tr * 8 + 4];
            float4 b0 = *(const float4*)&Bs[ss * BST + tc * 4];
            float4 b1 = *(const float4*)&Bs[ss * BST + 128 + tc * 4];
            unsigned long long bs[8] = {splat2(b0.x), splat2(b0.y), splat2(b0.z), splat2(b0.w),
                                        splat2(b1.x), splat2(b1.y), splat2(b1.z), splat2(b1.w)};
#pragma unroll
            for (int j = 0; j < 8; j++) {
                fma2(acc[0][j], a0.x, bs[j]);
                fma2(acc[1][j], a0.y, bs[j]);
                fma2(acc[2][j], a1.x, bs[j]);
                fma2(acc[3][j], a1.y, bs[j]);
            }
        }
        __syncthreads();
    }

    // ---- unpack, add precomputed bias scores, softmax ----
    float sc[8][8];
#pragma unroll
    for (int p = 0; p < 4; p++)
#pragma unroll
        for (int j = 0; j < 8; j++) {
            float2 u = unpk(acc[p][j]);
            sc[2 * p + 0][j] = u.x;
            sc[2 * p + 1][j] = u.y;
        }
    const float* sbrow = g_sb + ((size_t)((b * NH + h) * NM) + m0 + tr * 8) * NK;
#pragma unroll
    for (int r = 0; r < 8; r++) {
#pragma unroll
        for (int j = 0; j < 8; j++) {
            int col = (j < 4) ? (tc * 4 + j) : (128 + tc * 4 + (j - 4));
            sc[r][j] += sbrow[(size_t)r * NK + col];
        }
    }
#pragma unroll
    for (int r = 0; r < 8; r++) {
        float mx = sc[r][0];
#pragma unroll
        for (int j = 1; j < 8; j++) mx = fmaxf(mx, sc[r][j]);
#pragma unroll
        for (int off = 16; off > 0; off >>= 1)
            mx = fmaxf(mx, __shfl_xor_sync(0xffffffffu, mx, off));
        float sum = 0.f;
#pragma unroll
        for (int j = 0; j < 8; j++) { sc[r][j] = __expf(sc[r][j] - mx); sum += sc[r][j]; }
#pragma unroll
        for (int off = 16; off > 0; off >>= 1)
            sum += __shfl_xor_sync(0xffffffffu, sum, off);
        float inv = 1.f / sum;
#pragma unroll
        for (int j = 0; j < 8; j++) sc[r][j] *= inv;
    }

    // ---- attn to smem, then out = attn @ vproj ----
    float* attn = sm;               // [64][ATST] overlays As/Bs
    float* Vs = sm + 64 * ATST;     // [16][AST]
#pragma unroll
    for (int r = 0; r < 8; r++) {
#pragma unroll
        for (int j = 0; j < 8; j++) {
            int col = (j < 4) ? (tc * 4 + j) : (128 + tc * 4 + (j - 4));
            attn[(tr * 8 + r) * ATST + col] = sc[r][j];
        }
    }

    const int r2 = tid >> 4, c2 = tid & 15;
    const float* vp = g_vp + (size_t)b * NK * ND + h * NDH;
    float o[4][4];
#pragma unroll
    for (int i = 0; i < 4; i++)
#pragma unroll
        for (int j = 0; j < 4; j++) o[i][j] = 0.f;

    for (int k0 = 0; k0 < NK; k0 += 16) {
        __syncthreads();
        *(float4*)&Vs[(tid >> 4) * AST + ((tid & 15) << 2)] =
            *(const float4*)(vp + (size_t)(k0 + (tid >> 4)) * ND + ((tid & 15) << 2));
        __syncthreads();
#pragma unroll
        for (int j = 0; j < 16; j++) {
            float4 bb = *(const float4*)&Vs[j * AST + c2 * 4];
            float a0 = attn[(r2 * 4 + 0) * ATST + k0 + j];
            float a1 = attn[(r2 * 4 + 1) * ATST + k0 + j];
            float a2 = attn[(r2 * 4 + 2) * ATST + k0 + j];
            float a3 = attn[(r2 * 4 + 3) * ATST + k0 + j];
            o[0][0] += a0 * bb.x; o[0][1] += a0 * bb.y; o[0][2] += a0 * bb.z; o[0][3] += a0 * bb.w;
            o[1][0] += a1 * bb.x; o[1][1] += a1 * bb.y; o[1][2] += a1 * bb.z; o[1][3] += a1 * bb.w;
            o[2][0] += a2 * bb.x; o[2][1] += a2 * bb.y; o[2][2] += a2 * bb.z; o[2][3] += a2 * bb.w;
            o[3][0] += a3 * bb.x; o[3][1] += a3 * bb.y; o[3][2] += a3 * bb.z; o[3][3] += a3 * bb.w;
        }
    }

    float* op = g_o + ((size_t)b * NM + m0) * ND + h * NDH;
#pragma unroll
    for (int i = 0; i < 4; i++) {
        float4 st = make_float4(o[i][0], o[i][1], o[i][2], o[i][3]);
        *(float4*)(op + (size_t)(r2 * 4 + i) * ND + c2 * 4) = st;
    }
}

// ---------------------------------------------------------------------------
extern "C" void kernel_launch(void* const* d_in, const int* in_sizes, int n_in,
                              void* d_out, int out_size)
{
    (void)out_size;
    const float* zp = nullptr;
    const float* geom = nullptr;
    const float* cont = nullptr;
    const float* W[4] = {nullptr, nullptr, nullptr, nullptr};
    const float* bias[4] = {nullptr, nullptr, nullptr, nullptr};
    const float* E[2] = {nullptr, nullptr};
    int wi = 0, bi = 0, ei = 0;
    for (int i = 0; i < n_in; i++) {
        long sz = (long)in_sizes[i];
        if (sz == (long)NB * NM * ND) {
            if (!zp) zp = (const float*)d_in[i];
        } else if (sz == (long)NB * NH * NM * NS) {
            if (!geom) geom = (const float*)d_in[i];
            else if (!cont) cont = (const float*)d_in[i];
        } else if (sz == (long)ND * ND) {
            if (wi < 4) W[wi++] = (const float*)d_in[i];
        } else if (sz == (long)ND) {
            if (bi < 4) bias[bi++] = (const float*)d_in[i];
        } else if (sz == (long)NK * NS) {
            if (ei < 2) E[ei++] = (const float*)d_in[i];
        }
    }
    float* out = (float*)d_out;

    float *q, *k, *v, *o, *sbp;
    cudaGetSymbolAddress((void**)&q, g_q);
    cudaGetSymbolAddress((void**)&k, g_k);
    cudaGetSymbolAddress((void**)&v, g_v);
    cudaGetSymbolAddress((void**)&o, g_o);
    cudaGetSymbolAddress((void**)&sbp, g_sb);

    cudaFuncSetAttribute(tc32_nt, cudaFuncAttributeMaxDynamicSharedMemorySize, TCSM);
    cudaFuncSetAttribute(attn2, cudaFuncAttributeMaxDynamicSharedMemorySize,
                         SMF_FLOATS * (int)sizeof(float));

    dim3 thr(256);
    // bias scores: (geom+cont)[65536,2048] @ Ek[256,2048]^T -> g_sb [65536,256]
    tc32_nt<<<dim3(NB * NH * NM / BM, NK / BN), thr, TCSM>>>(geom, cont, E[0], nullptr,
                                                             sbp, NK, NS);
    // q/k/v projections: z[4096,1024] @ W^T + b
    tc32_nt<<<dim3(NB * NM / BM, ND / BN), thr, TCSM>>>(zp, nullptr, W[0], bias[0], q, ND, ND);
    tc32_nt<<<dim3(NB * NM / BM, ND / BN), thr, TCSM>>>(zp, nullptr, W[1], bias[1], k, ND, ND);
    tc32_nt<<<dim3(NB * NM / BM, ND / BN), thr, TCSM>>>(zp, nullptr, W[2], bias[2], v, ND, ND);
    // Linformer projections (split-K x4) + reduce
    proj_nn2<<<dim3(NK / 128, ND / 128, 16), thr>>>(E[0], E[1]);
    proj_reduce<<<4 * NK * ND / 256, thr>>>();
    // fused attention
    attn2<<<dim3(NM / 64, NH, NB), thr, SMF_FLOATS * sizeof(float)>>>();
    // output projection
    tc32_nt<<<dim3(NB * NM / BM, ND / BN), thr, TCSM>>>(o, nullptr, W[3], bias[3], out, ND, ND);
}

// round 6
// speedup vs baseline: 5.1566x; 1.3908x over previous
#include <cuda_runtime.h>

#define NB 2
#define NH 16
#define NM 2048
#define ND 1024
#define NDH 64
#define NS 2048
#define NK 256

// Scratch (device globals; no allocations allowed)
__device__ float g_q[NB * NM * ND];
__device__ float g_k[NB * NM * ND];
__device__ float g_v[NB * NM * ND];
__device__ float g_o[NB * NM * ND];
__device__ float g_kp[NB * NK * ND];
__device__ float g_vp[NB * NK * ND];
__device__ float g_sb[NB * NH * NM * NK];          // bias scores [B,H,M,K] (67MB)
__device__ float g_pp[16 * NK * ND];               // proj split-K partials

// ---------------- packed f32x2 helpers (SIMT kernels) ----------------
static __device__ __forceinline__ unsigned long long splat2(float x) {
    unsigned long long r;
    asm("mov.b64 %0, {%1, %1};" : "=l"(r) : "f"(x));
    return r;
}
static __device__ __forceinline__ void fma2(unsigned long long &c,
                                            unsigned long long a,
                                            unsigned long long b) {
    asm("fma.rn.f32x2 %0, %1, %2, %0;" : "+l"(c) : "l"(a), "l"(b));
}
static __device__ __forceinline__ float2 unpk(unsigned long long v) {
    float2 f;
    asm("mov.b64 {%0, %1}, %2;" : "=f"(f.x), "=f"(f.y) : "l"(v));
    return f;
}

// ---------------- fp16 mma helpers ----------------
static __device__ __forceinline__ unsigned s2u(const void* p) {
    unsigned a;
    asm("{ .reg .u64 t; cvta.to.shared.u64 t, %1; cvt.u32.u64 %0, t; }" : "=r"(a) : "l"(p));
    return a;
}
static __device__ __forceinline__ unsigned pack2(float lo, float hi) {
    unsigned r;
    asm("cvt.rn.f16x2.f32 %0, %1, %2;" : "=r"(r) : "f"(hi), "f"(lo));
    return r;
}
static __device__ __forceinline__ void ldm4(unsigned* r, unsigned a) {
    asm volatile("ldmatrix.sync.aligned.m8n8.x4.shared.b16 {%0,%1,%2,%3}, [%4];"
                 : "=r"(r[0]), "=r"(r[1]), "=r"(r[2]), "=r"(r[3]) : "r"(a));
}
static __device__ __forceinline__ void mma16(float* c, const unsigned* a,
                                             unsigned b0, unsigned b1) {
    asm volatile(
        "mma.sync.aligned.m16n8k16.row.col.f32.f16.f16.f32 "
        "{%0,%1,%2,%3}, {%4,%5,%6,%7}, {%8,%9}, {%0,%1,%2,%3};"
        : "+f"(c[0]), "+f"(c[1]), "+f"(c[2]), "+f"(c[3])
        : "r"(a[0]), "r"(a[1]), "r"(a[2]), "r"(a[3]), "r"(b0), "r"(b1));
}

#define BM 128
#define BN 128
#define BK 64
#define BKH 72                         // padded half stride
#define TILEH (128 * BKH)              // 9216 halves per tile
#define SM16 (4 * TILEH * 2)           // 73728 bytes (2 bufs x (A+B))

// ---------------------------------------------------------------------------
// C tile [128x128] = (A (+A2)) @ B^T (+bias) via fp16 m16n8k16 mma, fp32 accum.
// A: [M,Kd] row-major fp32; B: [Nrows,Kd] row-major fp32; Kd % 64 == 0.
// 256 threads = 8 warps (2m x 4n); warp tile 64x32; ldmatrix fragments.
// ---------------------------------------------------------------------------
static __device__ __forceinline__ void tc16_body(
    const float* __restrict__ A, const float* __restrict__ A2,
    const float* __restrict__ Bm, const float* __restrict__ bias,
    float* __restrict__ C, int Nld, int Kd, int bx, int by)
{
    extern __shared__ unsigned short smh[];
    const unsigned sbase = s2u(smh);
    const int tid = threadIdx.x, lane = tid & 31, wid = tid >> 5;
    const size_t m0 = (size_t)bx * BM;
    const int n0 = by * BN;

    // loader mapping: row group (tid>>3) + 32*j, col chunk (tid&7)*8 (2 float4)
    const int ldr = tid >> 3, ldc = (tid & 7) * 8;
    const float* Ag = A + (m0 + ldr) * (size_t)Kd + ldc;
    const float* A2g = A2 ? A2 + (m0 + ldr) * (size_t)Kd + ldc : (const float*)0;
    const float* Bg = Bm + (size_t)(n0 + ldr) * Kd + ldc;
    const unsigned sOff = (unsigned)(ldr * BKH + ldc) * 2;   // byte offset in tile

    auto ld = [&](int k0, int buf) {
        unsigned ab = sbase + (unsigned)(buf * 2 * TILEH) * 2 + sOff;
        unsigned bb = ab + (unsigned)TILEH * 2;
#pragma unroll
        for (int j = 0; j < 4; j++) {
            const size_t ro = (size_t)(j * 32) * Kd;
            const unsigned so = (unsigned)(j * 32 * BKH) * 2;
#pragma unroll
            for (int h = 0; h < 2; h++) {
                float4 v = *(const float4*)(Ag + ro + k0 + h * 4);
                if (A2g) {
                    float4 w = *(const float4*)(A2g + ro + k0 + h * 4);
                    v.x += w.x; v.y += w.y; v.z += w.z; v.w += w.w;
                }
                unsigned u0 = pack2(v.x, v.y), u1 = pack2(v.z, v.w);
                asm volatile("st.shared.v2.b32 [%0], {%1,%2};"
                             :: "r"(ab + so + h * 8), "r"(u0), "r"(u1) : "memory");
                float4 t = *(const float4*)(Bg + ro + k0 + h * 4);
                unsigned w0 = pack2(t.x, t.y), w1 = pack2(t.z, t.w);
                asm volatile("st.shared.v2.b32 [%0], {%1,%2};"
                             :: "r"(bb + so + h * 8), "r"(w0), "r"(w1) : "memory");
            }
        }
    };

    const int wm = (wid >> 2) * 64, wn = (wid & 3) * 32;
    const int gr = lane >> 2, gc = lane & 3;
    // ldmatrix address components (halves): row = (lane&15), col = (lane>>4)*8
    const unsigned frow = (unsigned)(lane & 15), fcol = (unsigned)((lane >> 4) * 8);

    float acc[4][4][4];
#pragma unroll
    for (int mt = 0; mt < 4; mt++)
#pragma unroll
        for (int nt = 0; nt < 4; nt++)
#pragma unroll
            for (int e = 0; e < 4; e++) acc[mt][nt][e] = 0.f;

    ld(0, 0);
    __syncthreads();

    const int nk = Kd / BK;
    for (int i = 0; i < nk; i++) {
        if (i + 1 < nk) ld((i + 1) * BK, (i + 1) & 1);
        const unsigned tb = sbase + (unsigned)((i & 1) * 2 * TILEH) * 2;
#pragma unroll
        for (int k16 = 0; k16 < BK; k16 += 16) {
            unsigned af[4][4], bf[4][2];
#pragma unroll
            for (int mt = 0; mt < 4; mt++) {
                unsigned a = tb + ((unsigned)(wm + mt * 16 + frow) * BKH + k16 + fcol) * 2;
                ldm4(af[mt], a);
            }
#pragma unroll
            for (int np = 0; np < 2; np++) {
                unsigned a = tb + (unsigned)TILEH * 2 +
                             ((unsigned)(wn + np * 16 + frow) * BKH + k16 + fcol) * 2;
                unsigned r[4];
                ldm4(r, a);
                bf[2 * np + 0][0] = r[0]; bf[2 * np + 1][0] = r[1];
                bf[2 * np + 0][1] = r[2]; bf[2 * np + 1][1] = r[3];
            }
#pragma unroll
            for (int mt = 0; mt < 4; mt++)
#pragma unroll
                for (int nt = 0; nt < 4; nt++)
                    mma16(acc[mt][nt], af[mt], bf[nt][0], bf[nt][1]);
        }
        __syncthreads();
    }

    // epilogue (m16n8 C layout: c0,c1 -> row gr; c2,c3 -> row gr+8; cols 2*gc,+1)
#pragma unroll
    for (int mt = 0; mt < 4; mt++) {
        const size_t r = m0 + wm + mt * 16 + gr;
        float* cp0 = C + r * (size_t)Nld;
        float* cp1 = C + (r + 8) * (size_t)Nld;
#pragma unroll
        for (int nt = 0; nt < 4; nt++) {
            const int c = n0 + wn + nt * 8 + 2 * gc;
            float b0 = bias ? bias[c] : 0.f;
            float b1 = bias ? bias[c + 1] : 0.f;
            *(float2*)(cp0 + c) = make_float2(acc[mt][nt][0] + b0, acc[mt][nt][1] + b1);
            *(float2*)(cp1 + c) = make_float2(acc[mt][nt][2] + b0, acc[mt][nt][3] + b1);
        }
    }
}

__global__ __launch_bounds__(256) void k_bias16(const float* __restrict__ geom,
                                               const float* __restrict__ cont,
                                               const float* __restrict__ Ek,
                                               float* __restrict__ sb)
{
    tc16_body(geom, cont, Ek, nullptr, sb, NK, NS, blockIdx.x, blockIdx.y);
}

__global__ __launch_bounds__(256) void k_qkv16(const float* __restrict__ z,
                                               const float* __restrict__ W0,
                                               const float* __restrict__ W1,
                                               const float* __restrict__ W2,
                                               const float* __restrict__ b0,
                                               const float* __restrict__ b1,
                                               const float* __restrict__ b2)
{
    const int zz = blockIdx.z;
    const float* W = (zz == 0) ? W0 : (zz == 1) ? W1 : W2;
    const float* bb = (zz == 0) ? b0 : (zz == 1) ? b1 : b2;
    float* C = (zz == 0) ? g_q : (zz == 1) ? g_k : g_v;
    tc16_body(z, nullptr, W, bb, C, ND, ND, blockIdx.x, blockIdx.y);
}

__global__ __launch_bounds__(256) void k_out16(const float* __restrict__ Wo,
                                               const float* __restrict__ bo,
                                               float* __restrict__ out)
{
    tc16_body(g_o, nullptr, Wo, bo, out, ND, ND, blockIdx.x, blockIdx.y);
}

// ---------------------------------------------------------------------------
// Linformer projections with split-K x4 (deterministic):
// bz = gemm*4 + split; gemm 0,1: Ek@k[b]; 2,3: Ev@v[b]. Partial -> g_pp[bz].
// ---------------------------------------------------------------------------
__global__ __launch_bounds__(256) void proj_nn2(const float* __restrict__ Ekm,
                                                const float* __restrict__ Evm)
{
    __shared__ float As[8][132];
    __shared__ float Bs[8][132];
    const int tid = threadIdx.x;
    const int bz = blockIdx.z;
    const int zz = bz >> 2, sp = bz & 3;
    const int kstart = sp * 512;
    const float* A = (zz < 2) ? Ekm : Evm;
    const float* Bm = ((zz < 2) ? g_k : g_v) + (size_t)(zz & 1) * NM * ND;
    float* C = g_pp + (size_t)bz * (NK * ND);
    const int Kd = NM, Nd = ND;
    const int bm = blockIdx.x * 128, bn = blockIdx.y * 128;
    const int tr = tid >> 4, tc = tid & 15;
    const int lr = tid >> 1, lk = (tid & 1) << 2;
    const int br = tid >> 5, bc = (tid & 31) << 2;

    unsigned long long acc[2][2][8];
#pragma unroll
    for (int a = 0; a < 2; a++)
#pragma unroll
        for (int p = 0; p < 2; p++)
#pragma unroll
            for (int j = 0; j < 8; j++) acc[a][p][j] = 0ull;

    const float* Ap = A + (size_t)(bm + lr) * Kd + kstart + lk;

    for (int kt = 0; kt < 512; kt += 8) {
        float4 av = *(const float4*)(Ap + kt);
        As[lk + 0][lr] = av.x; As[lk + 1][lr] = av.y;
        As[lk + 2][lr] = av.z; As[lk + 3][lr] = av.w;
        float4 bv = *(const float4*)(Bm + (size_t)(kstart + kt + br) * Nd + bn + bc);
        *(float4*)&Bs[br][bc] = bv;
        __syncthreads();
#pragma unroll
        for (int k = 0; k < 8; k++) {
            ulonglong2 a0 = *(const ulonglong2*)&As[k][tr * 4];
            ulonglong2 a1 = *(const ulonglong2*)&As[k][64 + tr * 4];
            float4 b0 = *(const float4*)&Bs[k][tc * 4];
            float4 b1 = *(const float4*)&Bs[k][64 + tc * 4];
            unsigned long long bs[8] = {splat2(b0.x), splat2(b0.y), splat2(b0.z), splat2(b0.w),
                                        splat2(b1.x), splat2(b1.y), splat2(b1.z), splat2(b1.w)};
#pragma unroll
            for (int j = 0; j < 8; j++) {
                fma2(acc[0][0][j], a0.x, bs[j]);
                fma2(acc[0][1][j], a0.y, bs[j]);
                fma2(acc[1][0][j], a1.x, bs[j]);
                fma2(acc[1][1][j], a1.y, bs[j]);
            }
        }
        __syncthreads();
    }

    float accf[2][4][8];
#pragma unroll
    for (int a = 0; a < 2; a++)
#pragma unroll
        for (int p = 0; p < 2; p++)
#pragma unroll
            for (int j = 0; j < 8; j++) {
                float2 u = unpk(acc[a][p][j]);
                accf[a][p * 2 + 0][j] = u.x;
                accf[a][p * 2 + 1][j] = u.y;
            }
#pragma unroll
    for (int a = 0; a < 2; a++)
#pragma unroll
        for (int rr = 0; rr < 4; rr++) {
            int row = bm + a * 64 + tr * 4 + rr;
            float* cp = C + (size_t)row * Nd + bn;
#pragma unroll
            for (int ch = 0; ch < 2; ch++) {
                int cb = ch * 64 + tc * 4;
                float4 o;
                o.x = accf[a][rr][ch * 4 + 0];
                o.y = accf[a][rr][ch * 4 + 1];
                o.z = accf[a][rr][ch * 4 + 2];
                o.w = accf[a][rr][ch * 4 + 3];
                *(float4*)(cp + cb) = o;
            }
        }
}

__global__ __launch_bounds__(256) void proj_reduce()
{
    const size_t i = (size_t)blockIdx.x * 256 + threadIdx.x;   // over 4*NK*ND
    const int zz = (int)(i / (NK * ND));
    const size_t r = i - (size_t)zz * (NK * ND);
    const size_t base = (size_t)(zz * 4) * (NK * ND) + r;
    float s = g_pp[base] + g_pp[base + (size_t)NK * ND] +
              g_pp[base + 2 * (size_t)NK * ND] + g_pp[base + 3 * (size_t)NK * ND];
    float* dst = (zz < 2) ? g_kp : g_vp;
    dst[(size_t)(zz & 1) * NK * ND + r] = s;
}

// ---------------------------------------------------------------------------
// Fused attention per (b, h, 64-row m tile):
//   scores[64,256] = g_sb (precomputed bias scores) + (q/8)[64,64] @ kproj^T
//   softmax over 256, out[64,64] = attn @ vproj  -> g_o (B,M,H,dh layout)
// ---------------------------------------------------------------------------
#define AST 72
#define BST 264
#define ATST 264
#define SMF_FLOATS (64 * ATST + 16 * AST)   // 18048 floats = 72192 B

__global__ __launch_bounds__(256) void attn2()
{
    extern __shared__ float sm[];
    float* As = sm;                 // [16][AST]
    float* Bs = sm + 16 * AST;      // [16][BST]
    const int m0 = blockIdx.x * 64;
    const int h = blockIdx.y, b = blockIdx.z;
    const int tid = threadIdx.x;
    const int tr = tid >> 5, tc = tid & 31;
    const int lrow = tid >> 2, lcg = (tid & 3) << 2;

    unsigned long long acc[4][8];
#pragma unroll
    for (int p = 0; p < 4; p++)
#pragma unroll
        for (int j = 0; j < 8; j++) acc[p][j] = 0ull;

    // ---- (q * 1/sqrt(dh)) @ kproj^T over dh=64 ----
    const float* qp = g_q + ((size_t)b * NM + m0) * ND + h * NDH;
    const float* kp = g_kp + ((size_t)b * NK + tid) * ND + h * NDH;
    for (int d0 = 0; d0 < NDH; d0 += 16) {
        const float* ep = kp + d0;
        float4 e0 = *(const float4*)(ep + 0);
        float4 e1 = *(const float4*)(ep + 4);
        float4 e2 = *(const float4*)(ep + 8);
        float4 e3 = *(const float4*)(ep + 12);
        Bs[0 * BST + tid] = e0.x;  Bs[1 * BST + tid] = e0.y;
        Bs[2 * BST + tid] = e0.z;  Bs[3 * BST + tid] = e0.w;
        Bs[4 * BST + tid] = e1.x;  Bs[5 * BST + tid] = e1.y;
        Bs[6 * BST + tid] = e1.z;  Bs[7 * BST + tid] = e1.w;
        Bs[8 * BST + tid] = e2.x;  Bs[9 * BST + tid] = e2.y;
        Bs[10 * BST + tid] = e2.z; Bs[11 * BST + tid] = e2.w;
        Bs[12 * BST + tid] = e3.x; Bs[13 * BST + tid] = e3.y;
        Bs[14 * BST + tid] = e3.z; Bs[15 * BST + tid] = e3.w;

        float4 qv = *(const float4*)(qp + (size_t)lrow * ND + d0 + lcg);
        As[(lcg + 0) * AST + lrow] = qv.x * 0.125f;
        As[(lcg + 1) * AST + lrow] = qv.y * 0.125f;
        As[(lcg + 2) * AST + lrow] = qv.z * 0.125f;
        As[(lcg + 3) * AST + lrow] = qv.w * 0.125f;
        __syncthreads();
#pragma unroll
        for (int ss = 0; ss < 16; ss++) {
            ulonglong2 a0 = *(const ulonglong2*)&As[ss * AST + tr * 8];
            ulonglong2 a1 = *(const ulonglong2*)&As[ss * AST + tr * 8 + 4];
            float4 b0 = *(const float4*)&Bs[ss * BST + tc * 4];
            float4 b1 = *(const float4*)&Bs[ss * BST + 128 + tc * 4];
            unsigned long long bs[8] = {splat2(b0.x), splat2(b0.y), splat2(b0.z), splat2(b0.w),
                                        splat2(b1.x), splat2(b1.y), splat2(b1.z), splat2(b1.w)};
#pragma unroll
            for (int j = 0; j < 8; j++) {
                fma2(acc[0][j], a0.x, bs[j]);
                fma2(acc[1][j], a0.y, bs[j]);
                fma2(acc[2][j], a1.x, bs[j]);
                fma2(acc[3][j], a1.y, bs[j]);
            }
        }
        __syncthreads();
    }

    // ---- unpack, add precomputed bias scores, softmax ----
    float sc[8][8];
#pragma unroll
    for (int p = 0; p < 4; p++)
#pragma unroll
        for (int j = 0; j < 8; j++) {
            float2 u = unpk(acc[p][j]);
            sc[2 * p + 0][j] = u.x;
            sc[2 * p + 1][j] = u.y;
        }
    const float* sbrow = g_sb + ((size_t)((b * NH + h) * NM) + m0 + tr * 8) * NK;
#pragma unroll
    for (int r = 0; r < 8; r++) {
#pragma unroll
        for (int j = 0; j < 8; j++) {
            int col = (j < 4) ? (tc * 4 + j) : (128 + tc * 4 + (j - 4));
            sc[r][j] += sbrow[(size_t)r * NK + col];
        }
    }
#pragma unroll
    for (int r = 0; r < 8; r++) {
        float mx = sc[r][0];
#pragma unroll
        for (int j = 1; j < 8; j++) mx = fmaxf(mx, sc[r][j]);
#pragma unroll
        for (int off = 16; off > 0; off >>= 1)
            mx = fmaxf(mx, __shfl_xor_sync(0xffffffffu, mx, off));
        float sum = 0.f;
#pragma unroll
        for (int j = 0; j < 8; j++) { sc[r][j] = __expf(sc[r][j] - mx); sum += sc[r][j]; }
#pragma unroll
        for (int off = 16; off > 0; off >>= 1)
            sum += __shfl_xor_sync(0xffffffffu, sum, off);
        float inv = 1.f / sum;
#pragma unroll
        for (int j = 0; j < 8; j++) sc[r][j] *= inv;
    }

    // ---- attn to smem, then out = attn @ vproj ----
    float* attn = sm;               // [64][ATST] overlays As/Bs
    float* Vs = sm + 64 * ATST;     // [16][AST]
#pragma unroll
    for (int r = 0; r < 8; r++) {
#pragma unroll
        for (int j = 0; j < 8; j++) {
            int col = (j < 4) ? (tc * 4 + j) : (128 + tc * 4 + (j - 4));
            attn[(tr * 8 + r) * ATST + col] = sc[r][j];
        }
    }

    const int r2 = tid >> 4, c2 = tid & 15;
    const float* vp = g_vp + (size_t)b * NK * ND + h * NDH;
    float o[4][4];
#pragma unroll
    for (int i = 0; i < 4; i++)
#pragma unroll
        for (int j = 0; j < 4; j++) o[i][j] = 0.f;

    for (int k0 = 0; k0 < NK; k0 += 16) {
        __syncthreads();
        *(float4*)&Vs[(tid >> 4) * AST + ((tid & 15) << 2)] =
            *(const float4*)(vp + (size_t)(k0 + (tid >> 4)) * ND + ((tid & 15) << 2));
        __syncthreads();
#pragma unroll
        for (int j = 0; j < 16; j++) {
            float4 bb = *(const float4*)&Vs[j * AST + c2 * 4];
            float a0 = attn[(r2 * 4 + 0) * ATST + k0 + j];
            float a1 = attn[(r2 * 4 + 1) * ATST + k0 + j];
            float a2 = attn[(r2 * 4 + 2) * ATST + k0 + j];
            float a3 = attn[(r2 * 4 + 3) * ATST + k0 + j];
            o[0][0] += a0 * bb.x; o[0][1] += a0 * bb.y; o[0][2] += a0 * bb.z; o[0][3] += a0 * bb.w;
            o[1][0] += a1 * bb.x; o[1][1] += a1 * bb.y; o[1][2] += a1 * bb.z; o[1][3] += a1 * bb.w;
            o[2][0] += a2 * bb.x; o[2][1] += a2 * bb.y; o[2][2] += a2 * bb.z; o[2][3] += a2 * bb.w;
            o[3][0] += a3 * bb.x; o[3][1] += a3 * bb.y; o[3][2] += a3 * bb.z; o[3][3] += a3 * bb.w;
        }
    }

    float* op = g_o + ((size_t)b * NM + m0) * ND + h * NDH;
#pragma unroll
    for (int i = 0; i < 4; i++) {
        float4 st = make_float4(o[i][0], o[i][1], o[i][2], o[i][3]);
        *(float4*)(op + (size_t)(r2 * 4 + i) * ND + c2 * 4) = st;
    }
}

// ---------------------------------------------------------------------------
extern "C" void kernel_launch(void* const* d_in, const int* in_sizes, int n_in,
                              void* d_out, int out_size)
{
    (void)out_size;
    const float* zp = nullptr;
    const float* geom = nullptr;
    const float* cont = nullptr;
    const float* W[4] = {nullptr, nullptr, nullptr, nullptr};
    const float* bias[4] = {nullptr, nullptr, nullptr, nullptr};
    const float* E[2] = {nullptr, nullptr};
    int wi = 0, bi = 0, ei = 0;
    for (int i = 0; i < n_in; i++) {
        long sz = (long)in_sizes[i];
        if (sz == (long)NB * NM * ND) {
            if (!zp) zp = (const float*)d_in[i];
        } else if (sz == (long)NB * NH * NM * NS) {
            if (!geom) geom = (const float*)d_in[i];
            else if (!cont) cont = (const float*)d_in[i];
        } else if (sz == (long)ND * ND) {
            if (wi < 4) W[wi++] = (const float*)d_in[i];
        } else if (sz == (long)ND) {
            if (bi < 4) bias[bi++] = (const float*)d_in[i];
        } else if (sz == (long)NK * NS) {
            if (ei < 2) E[ei++] = (const float*)d_in[i];
        }
    }
    float* out = (float*)d_out;

    float* sbp;
    cudaGetSymbolAddress((void**)&sbp, g_sb);

    cudaFuncSetAttribute(k_bias16, cudaFuncAttributeMaxDynamicSharedMemorySize, SM16);
    cudaFuncSetAttribute(k_qkv16, cudaFuncAttributeMaxDynamicSharedMemorySize, SM16);
    cudaFuncSetAttribute(k_out16, cudaFuncAttributeMaxDynamicSharedMemorySize, SM16);
    cudaFuncSetAttribute(attn2, cudaFuncAttributeMaxDynamicSharedMemorySize,
                         SMF_FLOATS * (int)sizeof(float));

    dim3 thr(256);
    // bias scores: (geom+cont)[65536,2048] @ Ek[256,2048]^T -> g_sb [65536,256]
    k_bias16<<<dim3(NB * NH * NM / BM, NK / BN), thr, SM16>>>(geom, cont, E[0], sbp);
    // q/k/v projections merged: z[4096,1024] @ W^T + b (grid.z selects)
    k_qkv16<<<dim3(NB * NM / BM, ND / BN, 3), thr, SM16>>>(zp, W[0], W[1], W[2],
                                                            bias[0], bias[1], bias[2]);
    // Linformer projections (split-K x4) + reduce
    proj_nn2<<<dim3(NK / 128, ND / 128, 16), thr>>>(E[0], E[1]);
    proj_reduce<<<4 * NK * ND / 256, thr>>>();
    // fused attention
    attn2<<<dim3(NM / 64, NH, NB), thr, SMF_FLOATS * sizeof(float)>>>();
    // output projection
    k_out16<<<dim3(NB * NM / BM, ND / BN), thr, SM16>>>(W[3], bias[3], out);
}

// round 7
// speedup vs baseline: 5.6138x; 1.0887x over previous
#include <cuda_runtime.h>

#define NB 2
#define NH 16
#define NM 2048
#define ND 1024
#define NDH 64
#define NS 2048
#define NK 256

// Scratch (device globals; no allocations allowed)
__device__ float g_q[NB * NM * ND];
__device__ float g_kt[NB * ND * NM];               // k transposed [b][d][m]
__device__ float g_vt[NB * ND * NM];               // v transposed [b][d][m]
__device__ float g_o[NB * NM * ND];
__device__ float g_kp[NB * NK * ND];
__device__ float g_vp[NB * NK * ND];
__device__ float g_sb[NB * NH * NM * NK];          // bias scores [B,H,M,K] (67MB)

// ---------------- packed f32x2 helpers (attn2) ----------------
static __device__ __forceinline__ unsigned long long splat2(float x) {
    unsigned long long r;
    asm("mov.b64 %0, {%1, %1};" : "=l"(r) : "f"(x));
    return r;
}
static __device__ __forceinline__ void fma2(unsigned long long &c,
                                            unsigned long long a,
                                            unsigned long long b) {
    asm("fma.rn.f32x2 %0, %1, %2, %0;" : "+l"(c) : "l"(a), "l"(b));
}
static __device__ __forceinline__ float2 unpk(unsigned long long v) {
    float2 f;
    asm("mov.b64 {%0, %1}, %2;" : "=f"(f.x), "=f"(f.y) : "l"(v));
    return f;
}

// ---------------- fp16 mma helpers ----------------
static __device__ __forceinline__ unsigned s2u(const void* p) {
    unsigned a;
    asm("{ .reg .u64 t; cvta.to.shared.u64 t, %1; cvt.u32.u64 %0, t; }" : "=r"(a) : "l"(p));
    return a;
}
static __device__ __forceinline__ unsigned pack2(float lo, float hi) {
    unsigned r;
    asm("cvt.rn.f16x2.f32 %0, %1, %2;" : "=r"(r) : "f"(hi), "f"(lo));
    return r;
}
static __device__ __forceinline__ void ldm4(unsigned* r, unsigned a) {
    asm volatile("ldmatrix.sync.aligned.m8n8.x4.shared.b16 {%0,%1,%2,%3}, [%4];"
                 : "=r"(r[0]), "=r"(r[1]), "=r"(r[2]), "=r"(r[3]) : "r"(a));
}
static __device__ __forceinline__ void mma16(float* c, const unsigned* a,
                                             unsigned b0, unsigned b1) {
    asm volatile(
        "mma.sync.aligned.m16n8k16.row.col.f32.f16.f16.f32 "
        "{%0,%1,%2,%3}, {%4,%5,%6,%7}, {%8,%9}, {%0,%1,%2,%3};"
        : "+f"(c[0]), "+f"(c[1]), "+f"(c[2]), "+f"(c[3])
        : "r"(a[0]), "r"(a[1]), "r"(a[2]), "r"(a[3]), "r"(b0), "r"(b1));
}

#define BM 128
#define BN 128
#define BK 64
#define BKH 72                         // padded half stride
#define TILEH (128 * BKH)              // 9216 halves per tile
#define SM16 (4 * TILEH * 2)           // 73728 bytes (2 bufs x (A+B))

// ---------------------------------------------------------------------------
// tc16_body: C tile [128x128] = A @ B^T (+bias) via fp16 m16n8k16, fp32 accum.
// If Ct != nullptr: instead of writing C, write transposed into
// Ct[(n0+c)*CtStride + m] (Ct pre-offset to this tile's m origin).
// ---------------------------------------------------------------------------
static __device__ __forceinline__ void tc16_body(
    const float* __restrict__ A, const float* __restrict__ Bm,
    const float* __restrict__ bias, float* __restrict__ C, int Nld, int Kd,
    int bx, int by, float* __restrict__ Ct, int CtStride)
{
    extern __shared__ unsigned short smh[];
    const unsigned sbase = s2u(smh);
    const int tid = threadIdx.x, lane = tid & 31, wid = tid >> 5;
    const size_t m0 = (size_t)bx * BM;
    const int n0 = by * BN;

    const int ldr = tid >> 3, ldc = (tid & 7) * 8;
    const float* Ag = A + (m0 + ldr) * (size_t)Kd + ldc;
    const float* Bg = Bm + (size_t)(n0 + ldr) * Kd + ldc;
    const unsigned sOff = (unsigned)(ldr * BKH + ldc) * 2;

    auto ld = [&](int k0, int buf) {
        unsigned ab = sbase + (unsigned)(buf * 2 * TILEH) * 2 + sOff;
        unsigned bb = ab + (unsigned)TILEH * 2;
#pragma unroll
        for (int j = 0; j < 4; j++) {
            const size_t ro = (size_t)(j * 32) * Kd;
            const unsigned so = (unsigned)(j * 32 * BKH) * 2;
#pragma unroll
            for (int h = 0; h < 2; h++) {
                float4 v = *(const float4*)(Ag + ro + k0 + h * 4);
                unsigned u0 = pack2(v.x, v.y), u1 = pack2(v.z, v.w);
                asm volatile("st.shared.v2.b32 [%0], {%1,%2};"
                             :: "r"(ab + so + h * 8), "r"(u0), "r"(u1) : "memory");
                float4 t = *(const float4*)(Bg + ro + k0 + h * 4);
                unsigned w0 = pack2(t.x, t.y), w1 = pack2(t.z, t.w);
                asm volatile("st.shared.v2.b32 [%0], {%1,%2};"
                             :: "r"(bb + so + h * 8), "r"(w0), "r"(w1) : "memory");
            }
        }
    };

    const int wm = (wid >> 2) * 64, wn = (wid & 3) * 32;
    const int gr = lane >> 2, gc = lane & 3;
    const unsigned frow = (unsigned)(lane & 15), fcol = (unsigned)((lane >> 4) * 8);

    float acc[4][4][4];
#pragma unroll
    for (int mt = 0; mt < 4; mt++)
#pragma unroll
        for (int nt = 0; nt < 4; nt++)
#pragma unroll
            for (int e = 0; e < 4; e++) acc[mt][nt][e] = 0.f;

    ld(0, 0);
    __syncthreads();

    const int nk = Kd / BK;
    for (int i = 0; i < nk; i++) {
        if (i + 1 < nk) ld((i + 1) * BK, (i + 1) & 1);
        const unsigned tb = sbase + (unsigned)((i & 1) * 2 * TILEH) * 2;
#pragma unroll
        for (int k16 = 0; k16 < BK; k16 += 16) {
            unsigned af[4][4], bf[4][2];
#pragma unroll
            for (int mt = 0; mt < 4; mt++) {
                unsigned a = tb + ((unsigned)(wm + mt * 16 + frow) * BKH + k16 + fcol) * 2;
                ldm4(af[mt], a);
            }
#pragma unroll
            for (int np = 0; np < 2; np++) {
                unsigned a = tb + (unsigned)TILEH * 2 +
                             ((unsigned)(wn + np * 16 + frow) * BKH + k16 + fcol) * 2;
                unsigned r[4];
                ldm4(r, a);
                bf[2 * np + 0][0] = r[0]; bf[2 * np + 1][0] = r[1];
                bf[2 * np + 0][1] = r[2]; bf[2 * np + 1][1] = r[3];
            }
#pragma unroll
            for (int mt = 0; mt < 4; mt++)
#pragma unroll
                for (int nt = 0; nt < 4; nt++)
                    mma16(acc[mt][nt], af[mt], bf[nt][0], bf[nt][1]);
        }
        __syncthreads();
    }

    if (!Ct) {
#pragma unroll
        for (int mt = 0; mt < 4; mt++) {
            const size_t r = m0 + wm + mt * 16 + gr;
            float* cp0 = C + r * (size_t)Nld;
            float* cp1 = C + (r + 8) * (size_t)Nld;
#pragma unroll
            for (int nt = 0; nt < 4; nt++) {
                const int c = n0 + wn + nt * 8 + 2 * gc;
                float b0 = bias ? bias[c] : 0.f;
                float b1 = bias ? bias[c + 1] : 0.f;
                *(float2*)(cp0 + c) = make_float2(acc[mt][nt][0] + b0, acc[mt][nt][1] + b1);
                *(float2*)(cp1 + c) = make_float2(acc[mt][nt][2] + b0, acc[mt][nt][3] + b1);
            }
        }
    } else {
        // transpose via smem stage: write Ct[(n0+c)*CtStride + m]
        float* st32 = (float*)smh;   // [128][132]
        __syncthreads();
#pragma unroll
        for (int mt = 0; mt < 4; mt++) {
            const int r0 = wm + mt * 16 + gr;
#pragma unroll
            for (int nt = 0; nt < 4; nt++) {
                const int c = wn + nt * 8 + 2 * gc;
                float b0 = bias ? bias[n0 + c] : 0.f;
                float b1 = bias ? bias[n0 + c + 1] : 0.f;
                st32[r0 * 132 + c] = acc[mt][nt][0] + b0;
                st32[r0 * 132 + c + 1] = acc[mt][nt][1] + b1;
                st32[(r0 + 8) * 132 + c] = acc[mt][nt][2] + b0;
                st32[(r0 + 8) * 132 + c + 1] = acc[mt][nt][3] + b1;
            }
        }
        __syncthreads();
#pragma unroll
        for (int i = 0; i < 16; i++) {
            const int c = wid * 16 + i;
            float4 o;
            o.x = st32[(lane * 4 + 0) * 132 + c];
            o.y = st32[(lane * 4 + 1) * 132 + c];
            o.z = st32[(lane * 4 + 2) * 132 + c];
            o.w = st32[(lane * 4 + 3) * 132 + c];
            *(float4*)(Ct + (size_t)(n0 + c) * CtStride + lane * 4) = o;
        }
        __syncthreads();
    }
}

__global__ __launch_bounds__(256) void k_qkv16(const float* __restrict__ z,
                                               const float* __restrict__ W0,
                                               const float* __restrict__ W1,
                                               const float* __restrict__ W2,
                                               const float* __restrict__ b0,
                                               const float* __restrict__ b1,
                                               const float* __restrict__ b2)
{
    const int zz = blockIdx.z;
    const float* W = (zz == 0) ? W0 : (zz == 1) ? W1 : W2;
    const float* bb = (zz == 0) ? b0 : (zz == 1) ? b1 : b2;
    if (zz == 0) {
        tc16_body(z, W, bb, g_q, ND, ND, blockIdx.x, blockIdx.y, nullptr, 0);
    } else {
        // write transposed: kt[b][d][m]
        const int b = blockIdx.x >> 4;                 // 16 m-tiles per batch
        const int mloc = (blockIdx.x & 15) * BM;
        float* base = ((zz == 1) ? g_kt : g_vt) + (size_t)b * ND * NM + mloc;
        tc16_body(z, W, bb, nullptr, 0, ND, blockIdx.x, blockIdx.y, base, NM);
    }
}

// proj: kp[b] = Ek @ kt[b]^T (NT), vp[b] = Ev @ vt[b]^T.  zz: 0,1->K 2,3->V
__global__ __launch_bounds__(256) void k_proj16(const float* __restrict__ Ek,
                                                const float* __restrict__ Ev)
{
    const int zz = blockIdx.z;
    const float* A = (zz < 2) ? Ek : Ev;
    const float* Bm = ((zz < 2) ? g_kt : g_vt) + (size_t)(zz & 1) * ND * NM;
    float* C = ((zz < 2) ? g_kp : g_vp) + (size_t)(zz & 1) * NK * ND;
    tc16_body(A, Bm, nullptr, C, ND, NM, blockIdx.x, blockIdx.y, nullptr, 0);
}

__global__ __launch_bounds__(256) void k_out16(const float* __restrict__ Wo,
                                               const float* __restrict__ bo,
                                               float* __restrict__ out)
{
    tc16_body(g_o, Wo, bo, out, ND, ND, blockIdx.x, blockIdx.y, nullptr, 0);
}

// ---------------------------------------------------------------------------
// k_bias256: 128x256 tile, single N pass over the full K=256 output width.
// C[m0..+128, 0..256] = (geom+cont) @ Ek^T.  Streams geom/cont exactly once.
// ---------------------------------------------------------------------------
#define B2_TA (128 * BKH)              // 9216 halves
#define B2_TB (256 * BKH)              // 18432 halves
#define B2_BUF (B2_TA + B2_TB)
#define SMB2 (2 * B2_BUF * 2)          // 110592 bytes

__global__ __launch_bounds__(256) void k_bias256(const float* __restrict__ geom,
                                                 const float* __restrict__ cont,
                                                 const float* __restrict__ Ek,
                                                 float* __restrict__ sb)
{
    extern __shared__ unsigned short smh[];
    const unsigned sbase = s2u(smh);
    const int tid = threadIdx.x, lane = tid & 31, wid = tid >> 5;
    const size_t m0 = (size_t)blockIdx.x * BM;

    const int ldr = tid >> 3, ldc = (tid & 7) * 8;
    const float* Ag = geom + (m0 + ldr) * (size_t)NS + ldc;
    const float* Cg = cont + (m0 + ldr) * (size_t)NS + ldc;
    const float* Bg = Ek + (size_t)ldr * NS + ldc;
    const unsigned sOff = (unsigned)(ldr * BKH + ldc) * 2;

    auto ld = [&](int k0, int buf) {
        unsigned ab = sbase + (unsigned)(buf * B2_BUF) * 2 + sOff;
        unsigned bb = sbase + (unsigned)(buf * B2_BUF + B2_TA) * 2 + sOff;
#pragma unroll
        for (int j = 0; j < 4; j++) {
            const size_t ro = (size_t)(j * 32) * NS;
            const unsigned so = (unsigned)(j * 32 * BKH) * 2;
#pragma unroll
            for (int h = 0; h < 2; h++) {
                float4 v = *(const float4*)(Ag + ro + k0 + h * 4);
                float4 w = *(const float4*)(Cg + ro + k0 + h * 4);
                v.x += w.x; v.y += w.y; v.z += w.z; v.w += w.w;
                unsigned u0 = pack2(v.x, v.y), u1 = pack2(v.z, v.w);
                asm volatile("st.shared.v2.b32 [%0], {%1,%2};"
                             :: "r"(ab + so + h * 8), "r"(u0), "r"(u1) : "memory");
            }
        }
#pragma unroll
        for (int j = 0; j < 8; j++) {
            const size_t ro = (size_t)(j * 32) * NS;
            const unsigned so = (unsigned)(j * 32 * BKH) * 2;
#pragma unroll
            for (int h = 0; h < 2; h++) {
                float4 t = *(const float4*)(Bg + ro + k0 + h * 4);
                unsigned w0 = pack2(t.x, t.y), w1 = pack2(t.z, t.w);
                asm volatile("st.shared.v2.b32 [%0], {%1,%2};"
                             :: "r"(bb + so + h * 8), "r"(w0), "r"(w1) : "memory");
            }
        }
    };

    const int wm = (wid >> 2) * 64, wn = (wid & 3) * 64;
    const int gr = lane >> 2, gc = lane & 3;
    const unsigned frow = (unsigned)(lane & 15), fcol = (unsigned)((lane >> 4) * 8);

    float acc[4][8][4];
#pragma unroll
    for (int mt = 0; mt < 4; mt++)
#pragma unroll
        for (int nt = 0; nt < 8; nt++)
#pragma unroll
            for (int e = 0; e < 4; e++) acc[mt][nt][e] = 0.f;

    ld(0, 0);
    __syncthreads();

    const int nk = NS / BK;   // 32
    for (int i = 0; i < nk; i++) {
        if (i + 1 < nk) ld((i + 1) * BK, (i + 1) & 1);
        const unsigned ta = sbase + (unsigned)((i & 1) * B2_BUF) * 2;
        const unsigned tbB = sbase + (unsigned)((i & 1) * B2_BUF + B2_TA) * 2;
#pragma unroll
        for (int k16 = 0; k16 < BK; k16 += 16) {
            unsigned af[4][4], bf[8][2];
#pragma unroll
            for (int mt = 0; mt < 4; mt++) {
                unsigned a = ta + ((unsigned)(wm + mt * 16 + frow) * BKH + k16 + fcol) * 2;
                ldm4(af[mt], a);
            }
#pragma unroll
            for (int np = 0; np < 4; np++) {
                unsigned a = tbB + ((unsigned)(wn + np * 16 + frow) * BKH + k16 + fcol) * 2;
                unsigned r[4];
                ldm4(r, a);
                bf[2 * np + 0][0] = r[0]; bf[2 * np + 1][0] = r[1];
                bf[2 * np + 0][1] = r[2]; bf[2 * np + 1][1] = r[3];
            }
#pragma unroll
            for (int mt = 0; mt < 4; mt++)
#pragma unroll
                for (int nt = 0; nt < 8; nt++)
                    mma16(acc[mt][nt], af[mt], bf[nt][0], bf[nt][1]);
        }
        __syncthreads();
    }

#pragma unroll
    for (int mt = 0; mt < 4; mt++) {
        const size_t r = m0 + wm + mt * 16 + gr;
        float* cp0 = sb + r * (size_t)NK;
        float* cp1 = sb + (r + 8) * (size_t)NK;
#pragma unroll
        for (int nt = 0; nt < 8; nt++) {
            const int c = wn + nt * 8 + 2 * gc;
            *(float2*)(cp0 + c) = make_float2(acc[mt][nt][0], acc[mt][nt][1]);
            *(float2*)(cp1 + c) = make_float2(acc[mt][nt][2], acc[mt][nt][3]);
        }
    }
}

// ---------------------------------------------------------------------------
// Fused attention per (b, h, 64-row m tile):
//   scores[64,256] = g_sb + (q/8)[64,64] @ kproj^T ; softmax; attn @ vproj
// ---------------------------------------------------------------------------
#define AST 72
#define BST 264
#define ATST 264
#define SMF_FLOATS (64 * ATST + 16 * AST)   // 18048 floats = 72192 B

__global__ __launch_bounds__(256) void attn2()
{
    extern __shared__ float sm[];
    float* As = sm;                 // [16][AST]
    float* Bs = sm + 16 * AST;      // [16][BST]
    const int m0 = blockIdx.x * 64;
    const int h = blockIdx.y, b = blockIdx.z;
    const int tid = threadIdx.x;
    const int tr = tid >> 5, tc = tid & 31;
    const int lrow = tid >> 2, lcg = (tid & 3) << 2;

    unsigned long long acc[4][8];
#pragma unroll
    for (int p = 0; p < 4; p++)
#pragma unroll
        for (int j = 0; j < 8; j++) acc[p][j] = 0ull;

    const float* qp = g_q + ((size_t)b * NM + m0) * ND + h * NDH;
    const float* kp = g_kp + ((size_t)b * NK + tid) * ND + h * NDH;
    for (int d0 = 0; d0 < NDH; d0 += 16) {
        const float* ep = kp + d0;
        float4 e0 = *(const float4*)(ep + 0);
        float4 e1 = *(const float4*)(ep + 4);
        float4 e2 = *(const float4*)(ep + 8);
        float4 e3 = *(const float4*)(ep + 12);
        Bs[0 * BST + tid] = e0.x;  Bs[1 * BST + tid] = e0.y;
        Bs[2 * BST + tid] = e0.z;  Bs[3 * BST + tid] = e0.w;
        Bs[4 * BST + tid] = e1.x;  Bs[5 * BST + tid] = e1.y;
        Bs[6 * BST + tid] = e1.z;  Bs[7 * BST + tid] = e1.w;
        Bs[8 * BST + tid] = e2.x;  Bs[9 * BST + tid] = e2.y;
        Bs[10 * BST + tid] = e2.z; Bs[11 * BST + tid] = e2.w;
        Bs[12 * BST + tid] = e3.x; Bs[13 * BST + tid] = e3.y;
        Bs[14 * BST + tid] = e3.z; Bs[15 * BST + tid] = e3.w;

        float4 qv = *(const float4*)(qp + (size_t)lrow * ND + d0 + lcg);
        As[(lcg + 0) * AST + lrow] = qv.x * 0.125f;
        As[(lcg + 1) * AST + lrow] = qv.y * 0.125f;
        As[(lcg + 2) * AST + lrow] = qv.z * 0.125f;
        As[(lcg + 3) * AST + lrow] = qv.w * 0.125f;
        __syncthreads();
#pragma unroll
        for (int ss = 0; ss < 16; ss++) {
            ulonglong2 a0 = *(const ulonglong2*)&As[ss * AST + tr * 8];
            ulonglong2 a1 = *(const ulonglong2*)&As[ss * AST + tr * 8 + 4];
            float4 b0 = *(const float4*)&Bs[ss * BST + tc * 4];
            float4 b1 = *(const float4*)&Bs[ss * BST + 128 + tc * 4];
            unsigned long long bs[8] = {splat2(b0.x), splat2(b0.y), splat2(b0.z), splat2(b0.w),
                                        splat2(b1.x), splat2(b1.y), splat2(b1.z), splat2(b1.w)};
#pragma unroll
            for (int j = 0; j < 8; j++) {
                fma2(acc[0][j], a0.x, bs[j]);
                fma2(acc[1][j], a0.y, bs[j]);
                fma2(acc[2][j], a1.x, bs[j]);
                fma2(acc[3][j], a1.y, bs[j]);
            }
        }
        __syncthreads();
    }

    float sc[8][8];
#pragma unroll
    for (int p = 0; p < 4; p++)
#pragma unroll
        for (int j = 0; j < 8; j++) {
            float2 u = unpk(acc[p][j]);
            sc[2 * p + 0][j] = u.x;
            sc[2 * p + 1][j] = u.y;
        }
    const float* sbrow = g_sb + ((size_t)((b * NH + h) * NM) + m0 + tr * 8) * NK;
#pragma unroll
    for (int r = 0; r < 8; r++) {
#pragma unroll
        for (int j = 0; j < 8; j++) {
            int col = (j < 4) ? (tc * 4 + j) : (128 + tc * 4 + (j - 4));
            sc[r][j] += sbrow[(size_t)r * NK + col];
        }
    }
#pragma unroll
    for (int r = 0; r < 8; r++) {
        float mx = sc[r][0];
#pragma unroll
        for (int j = 1; j < 8; j++) mx = fmaxf(mx, sc[r][j]);
#pragma unroll
        for (int off = 16; off > 0; off >>= 1)
            mx = fmaxf(mx, __shfl_xor_sync(0xffffffffu, mx, off));
        float sum = 0.f;
#pragma unroll
        for (int j = 0; j < 8; j++) { sc[r][j] = __expf(sc[r][j] - mx); sum += sc[r][j]; }
#pragma unroll
        for (int off = 16; off > 0; off >>= 1)
            sum += __shfl_xor_sync(0xffffffffu, sum, off);
        float inv = 1.f / sum;
#pragma unroll
        for (int j = 0; j < 8; j++) sc[r][j] *= inv;
    }

    float* attn = sm;               // [64][ATST] overlays As/Bs
    float* Vs = sm + 64 * ATST;     // [16][AST]
#pragma unroll
    for (int r = 0; r < 8; r++) {
#pragma unroll
        for (int j = 0; j < 8; j++) {
            int col = (j < 4) ? (tc * 4 + j) : (128 + tc * 4 + (j - 4));
            attn[(tr * 8 + r) * ATST + col] = sc[r][j];
        }
    }

    const int r2 = tid >> 4, c2 = tid & 15;
    const float* vp = g_vp + (size_t)b * NK * ND + h * NDH;
    float o[4][4];
#pragma unroll
    for (int i = 0; i < 4; i++)
#pragma unroll
        for (int j = 0; j < 4; j++) o[i][j] = 0.f;

    for (int k0 = 0; k0 < NK; k0 += 16) {
        __syncthreads();
        *(float4*)&Vs[(tid >> 4) * AST + ((tid & 15) << 2)] =
            *(const float4*)(vp + (size_t)(k0 + (tid >> 4)) * ND + ((tid & 15) << 2));
        __syncthreads();
#pragma unroll
        for (int j = 0; j < 16; j++) {
            float4 bb = *(const float4*)&Vs[j * AST + c2 * 4];
            float a0 = attn[(r2 * 4 + 0) * ATST + k0 + j];
            float a1 = attn[(r2 * 4 + 1) * ATST + k0 + j];
            float a2 = attn[(r2 * 4 + 2) * ATST + k0 + j];
            float a3 = attn[(r2 * 4 + 3) * ATST + k0 + j];
            o[0][0] += a0 * bb.x; o[0][1] += a0 * bb.y; o[0][2] += a0 * bb.z; o[0][3] += a0 * bb.w;
            o[1][0] += a1 * bb.x; o[1][1] += a1 * bb.y; o[1][2] += a1 * bb.z; o[1][3] += a1 * bb.w;
            o[2][0] += a2 * bb.x; o[2][1] += a2 * bb.y; o[2][2] += a2 * bb.z; o[2][3] += a2 * bb.w;
            o[3][0] += a3 * bb.x; o[3][1] += a3 * bb.y; o[3][2] += a3 * bb.z; o[3][3] += a3 * bb.w;
        }
    }

    float* op = g_o + ((size_t)b * NM + m0) * ND + h * NDH;
#pragma unroll
    for (int i = 0; i < 4; i++) {
        float4 st = make_float4(o[i][0], o[i][1], o[i][2], o[i][3]);
        *(float4*)(op + (size_t)(r2 * 4 + i) * ND + c2 * 4) = st;
    }
}

// ---------------------------------------------------------------------------
extern "C" void kernel_launch(void* const* d_in, const int* in_sizes, int n_in,
                              void* d_out, int out_size)
{
    (void)out_size;
    const float* zp = nullptr;
    const float* geom = nullptr;
    const float* cont = nullptr;
    const float* W[4] = {nullptr, nullptr, nullptr, nullptr};
    const float* bias[4] = {nullptr, nullptr, nullptr, nullptr};
    const float* E[2] = {nullptr, nullptr};
    int wi = 0, bi = 0, ei = 0;
    for (int i = 0; i < n_in; i++) {
        long sz = (long)in_sizes[i];
        if (sz == (long)NB * NM * ND) {
            if (!zp) zp = (const float*)d_in[i];
        } else if (sz == (long)NB * NH * NM * NS) {
            if (!geom) geom = (const float*)d_in[i];
            else if (!cont) cont = (const float*)d_in[i];
        } else if (sz == (long)ND * ND) {
            if (wi < 4) W[wi++] = (const float*)d_in[i];
        } else if (sz == (long)ND) {
            if (bi < 4) bias[bi++] = (const float*)d_in[i];
        } else if (sz == (long)NK * NS) {
            if (ei < 2) E[ei++] = (const float*)d_in[i];
        }
    }
    float* out = (float*)d_out;

    float* sbp;
    cudaGetSymbolAddress((void**)&sbp, g_sb);

    cudaFuncSetAttribute(k_bias256, cudaFuncAttributeMaxDynamicSharedMemorySize, SMB2);
    cudaFuncSetAttribute(k_qkv16, cudaFuncAttributeMaxDynamicSharedMemorySize, SM16);
    cudaFuncSetAttribute(k_proj16, cudaFuncAttributeMaxDynamicSharedMemorySize, SM16);
    cudaFuncSetAttribute(k_out16, cudaFuncAttributeMaxDynamicSharedMemorySize, SM16);
    cudaFuncSetAttribute(attn2, cudaFuncAttributeMaxDynamicSharedMemorySize,
                         SMF_FLOATS * (int)sizeof(float));

    dim3 thr(256);
    // bias scores: (geom+cont)[65536,2048] @ Ek^T -> g_sb, single pass over A
    k_bias256<<<dim3(NB * NH * NM / BM, 1), thr, SMB2>>>(geom, cont, E[0], sbp);
    // q/k/v projections; k,v written transposed for the proj NT GEMM
    k_qkv16<<<dim3(NB * NM / BM, ND / BN, 3), thr, SM16>>>(zp, W[0], W[1], W[2],
                                                            bias[0], bias[1], bias[2]);
    // Linformer projections as NT GEMMs on tensor cores
    k_proj16<<<dim3(NK / BM, ND / BN, 4), thr, SM16>>>(E[0], E[1]);
    // fused attention
    attn2<<<dim3(NM / 64, NH, NB), thr, SMF_FLOATS * sizeof(float)>>>();
    // output projection
    k_out16<<<dim3(NB * NM / BM, ND / BN), thr, SM16>>>(W[3], bias[3], out);
}